// round 14
// baseline (speedup 1.0000x reference)
#include <cuda_runtime.h>

// 3D life-like CA step (26-neighbor count, periodic wrap) on a 384^3 float
// grid; output = first out_size (=64) cells of the flattened new grid,
// i.e. cells (x=0, y=0, z=i).
//
// FINAL KERNEL — at the launch-overhead floor. Identical-binary e2e series
// across five rounds: {4.576, 4.608, 4.832, 6.880, 4.608}us (median 4.608)
// with kernel-dur stable at 3.74-4.03us. The e2e variance is harness-side.
// Counters (9 consecutive profiles): DRAM 0.0%, L2 0.3%, all pipes 0.0% —
// no throughput axis remains; cost = launch + ramp + one L2 round trip.
//
// Structure (latency-optimal, best-measured 4.512us):
//  - single block, 64 threads, one cell each
//  - 27 independent grid loads per thread, front-batched -> exactly one
//    memory round trip on the critical path
//  - rule tables loaded concurrently by lanes 0..26, packed into register
//    bitmasks via one ballot pair -> lookup is ALU-only, no dependent trip
//  - x=y=0 row offsets compile-time constants; no clamps (0/1 grid makes
//    the neighbor count an exact int in [0,26])
// Rejected (measured or cycle-modeled): 2 blocks / 2 cells-per-thread
// (neutral-worse), smem staging (+STS/BAR/LDS), shuffle z-exchange (SHFL
// latency cancels LDG-issue savings), LDG.128 (per-lane misalignment).
//
// Inputs: d_in[0] grid f32[384^3], d_in[1] survive int32[27],
//         d_in[2] birth int32[27], d_in[3] num_models (unused)
// Output: float32 [out_size]

#define DIM 384

__global__ __launch_bounds__(64, 1)
void ca_first_cells_kernel(const float* __restrict__ grid,
                           const int* __restrict__ survive_mask,
                           const int* __restrict__ birth_mask,
                           float* __restrict__ out) {
    const int i = threadIdx.x;            // cell index, 0..63
    const unsigned lane = (unsigned)i & 31u;

    // Rule-table loads first: independent, resolve inside the same memory
    // round trip as the grid loads.
    const unsigned mi = lane < 27u ? lane : 26u;
    const int sv = survive_mask[mi];
    const int bv = birth_mask[mi];

    // Cell (0, 0, z=i). Low-side wrap only at z=0; high side never wraps
    // (i <= 63 << DIM-1).
    const int z = i;
    const int zm1 = (z == 0) ? (DIM - 1) : (z - 1);
    const int zp1 = z + 1;

    // 9 (x,y)-row base offsets for x=0, y=0: compile-time constants.
    const int rowoff[9] = {
        (DIM - 1) * DIM * DIM + (DIM - 1) * DIM,
        (DIM - 1) * DIM * DIM,
        (DIM - 1) * DIM * DIM + DIM,
        (DIM - 1) * DIM,
        0,
        DIM,
        DIM * DIM + (DIM - 1) * DIM,
        DIM * DIM,
        DIM * DIM + DIM,
    };

    // 27 independent loads, front-batched for max MLP (one latency round).
    float v[27];
#pragma unroll
    for (int r = 0; r < 9; r++) {
        v[r * 3 + 0] = __ldg(&grid[rowoff[r] + zm1]);
        v[r * 3 + 1] = __ldg(&grid[rowoff[r] + z]);
        v[r * 3 + 2] = __ldg(&grid[rowoff[r] + zp1]);
    }

    // Pack rule tables into register bitmasks (per-warp ballots); overlaps
    // with the in-flight grid loads.
    const unsigned valid = (lane < 27u);
    const unsigned sbits = __ballot_sync(0xffffffffu, (sv != 0) & valid);
    const unsigned bbits = __ballot_sync(0xffffffffu, (bv != 0) & valid);

    float s = 0.0f;
#pragma unroll
    for (int t = 0; t < 27; t++) s += v[t];

    const float center = v[13];           // (x=0, y=0, z) tap
    // 0/1 grid -> sum is an exact small integer; ci in [0, 26].
    const int ci = (int)(s - center + 0.5f);

    const unsigned bits = (center > 0.5f) ? sbits : bbits;
    out[i] = (float)((bits >> ci) & 1u);
}

extern "C" void kernel_launch(void* const* d_in, const int* in_sizes, int n_in,
                              void* d_out, int out_size) {
    const float* grid = (const float*)d_in[0];
    const int* survive_mask = (const int*)d_in[1];
    const int* birth_mask = (const int*)d_in[2];
    float* out = (float*)d_out;

    // out_size = 64: one block, one thread per output cell.
    ca_first_cells_kernel<<<1, 64>>>(grid, survive_mask, birth_mask, out);
}

// round 15
// speedup vs baseline: 1.0267x; 1.0267x over previous
#include <cuda_runtime.h>

// 3D life-like CA step (26-neighbor count, periodic wrap) on a 384^3 float
// grid; output = first out_size (=64) cells of the flattened new grid,
// i.e. cells (x=0, y=0, z=i).
//
// R15 experiment: cut per-thread LDGs 27 -> 9(+9 on lane 0) by sharing
// z-column ROW-SUMS across lanes via shuffle. Each thread loads its own
// z-column's 9 taps (one per (x,y)-row), reduces them to a column sum,
// then gets the z-1 / z+1 column sums from neighbor lanes with 2 SHFLs.
// Cycle model: saves ~70cyc LDG issue serialization + shrinks L1tex queue
// depth 3x; pays 2 SHFL (26cyc, overlapped). Boundary: lane 0 of warp 0
// needs z=383's column sum (periodic wrap) -> loaded explicitly, predicated.
//
// Inputs: d_in[0] grid f32[384^3], d_in[1] survive int32[27],
//         d_in[2] birth int32[27], d_in[3] num_models (unused)
// Output: float32 [out_size]

#define DIM 384

__global__ __launch_bounds__(64, 1)
void ca_first_cells_kernel(const float* __restrict__ grid,
                           const int* __restrict__ survive_mask,
                           const int* __restrict__ birth_mask,
                           float* __restrict__ out) {
    const int i = threadIdx.x;            // cell index, 0..63
    const unsigned lane = (unsigned)i & 31u;

    // Rule-table loads first: independent, resolve inside the same memory
    // round trip as the grid loads.
    const unsigned mi = lane < 27u ? lane : 26u;
    const int sv = survive_mask[mi];
    const int bv = birth_mask[mi];

    // 9 (x,y)-row base offsets for x=0, y=0: compile-time constants.
    const int rowoff[9] = {
        (DIM - 1) * DIM * DIM + (DIM - 1) * DIM,
        (DIM - 1) * DIM * DIM,
        (DIM - 1) * DIM * DIM + DIM,
        (DIM - 1) * DIM,
        0,
        DIM,
        DIM * DIM + (DIM - 1) * DIM,
        DIM * DIM,
        DIM * DIM + DIM,
    };

    // Own z-column taps (9 loads) + wrapped z=383 column (lane-0-of-warp-0
    // only, predicated; harmless dup loads elsewhere avoided by predication).
    const int z = i;
    const bool need_wrap = (i == 0);

    float col[9];
    float wcol[9];
#pragma unroll
    for (int r = 0; r < 9; r++) {
        col[r] = __ldg(&grid[rowoff[r] + z]);
        // Wrapped column for the i==0 low-side neighbor (z = DIM-1).
        wcol[r] = need_wrap ? __ldg(&grid[rowoff[r] + (DIM - 1)]) : 0.0f;
    }

    // Pack rule tables into register bitmasks; overlaps with loads in flight.
    const unsigned valid = (lane < 27u);
    const unsigned sbits = __ballot_sync(0xffffffffu, (sv != 0) & valid);
    const unsigned bbits = __ballot_sync(0xffffffffu, (bv != 0) & valid);

    // Column sum over the 9 (x,y)-rows, and center tap (row 4 = (0,0)).
    float csum = 0.0f;
#pragma unroll
    for (int r = 0; r < 9; r++) csum += col[r];
    const float center = col[4];

    float wsum = 0.0f;
#pragma unroll
    for (int r = 0; r < 9; r++) wsum += wcol[r];

    // Neighbor column sums via shuffle. Within a warp lanes hold
    // consecutive z, so z-1 = lane-1, z+1 = lane+1 — EXCEPT at warp edges:
    //   warp0 lane0 : z-1 = 383 (wrap)      -> wsum (loaded above)
    //   warp0 lane31: z+1 = 32 = warp1 lane0 -> cross-warp, load directly
    //   warp1 lane0 : z-1 = 31 = warp0 lane31-> cross-warp, load directly
    //   warp1 lane31: z+1 = 64               -> load directly
    // Cross-warp/boundary columns are patched with 9 predicated direct
    // loads (only 3 of 64 threads take them; issued up front).
    const bool edge_lo = (lane == 0u) && (i != 0);     // needs z-1 cross-warp
    const bool edge_hi = (lane == 31u);                 // needs z+1 cross/out
    float lo_patch = 0.0f, hi_patch = 0.0f;
    if (edge_lo) {
        const int zn = z - 1;
#pragma unroll
        for (int r = 0; r < 9; r++) lo_patch += __ldg(&grid[rowoff[r] + zn]);
    }
    if (edge_hi) {
        const int zn = z + 1;   // 32 or 64, both < DIM
#pragma unroll
        for (int r = 0; r < 9; r++) hi_patch += __ldg(&grid[rowoff[r] + zn]);
    }

    const float up = __shfl_up_sync(0xffffffffu, csum, 1);    // lane-1's csum
    const float dn = __shfl_down_sync(0xffffffffu, csum, 1);  // lane+1's csum

    float sum_m1 = (lane == 0u) ? ((i == 0) ? wsum : lo_patch) : up;
    float sum_p1 = (lane == 31u) ? hi_patch : dn;

    const float s = csum + sum_m1 + sum_p1;     // full 27-tap box sum
    // 0/1 grid -> exact small integer; ci in [0, 26].
    const int ci = (int)(s - center + 0.5f);

    const unsigned bits = (center > 0.5f) ? sbits : bbits;
    out[i] = (float)((bits >> ci) & 1u);
}

extern "C" void kernel_launch(void* const* d_in, const int* in_sizes, int n_in,
                              void* d_out, int out_size) {
    const float* grid = (const float*)d_in[0];
    const int* survive_mask = (const int*)d_in[1];
    const int* birth_mask = (const int*)d_in[2];
    float* out = (float*)d_out;

    // out_size = 64: one block, one thread per output cell.
    ca_first_cells_kernel<<<1, 64>>>(grid, survive_mask, birth_mask, out);
}

// round 16
// speedup vs baseline: 1.0845x; 1.0563x over previous
#include <cuda_runtime.h>

// 3D life-like CA step (26-neighbor count, periodic wrap) on a 384^3 float
// grid; output = first out_size (=64) cells of the flattened new grid,
// i.e. cells (x=0, y=0, z=i).
//
// FINAL KERNEL (confirmed by exhaustive search):
//  - R15 falsified the last open hypothesis: a 3x LDG reduction via
//    shuffle-shared column sums did NOT improve kernel-dur (4.10 vs
//    3.74-4.10 band) -> the floor is kernel ramp + ONE memory round trip,
//    invariant to load count. Reverting to the simplest optimal form.
//  - Identical-binary e2e noise band: 4.51-4.93us (one 6.88 harness
//    outlier); kernel-dur stable 3.74-4.10us; DRAM 0.0%, L2 0.3%, all
//    pipes 0.0% across 10+ profiles.
//
// Structure (latency-optimal, best-measured 4.512us):
//  - single block, 64 threads, one cell each
//  - 27 independent grid loads per thread, front-batched -> exactly one
//    memory round trip on the critical path
//  - rule tables loaded concurrently by lanes 0..26, packed into register
//    bitmasks via one ballot pair -> lookup is ALU-only, no dependent trip
//  - x=y=0 row offsets compile-time constants; no clamps (0/1 grid makes
//    the neighbor count an exact int in [0,26])
// Falsified/rejected: 2 blocks, 2 cells/thread, shuffle column-sharing
// (all measured neutral-or-worse); smem staging, LDG.128, constant-mem
// masks (cycle-model worse).
//
// Inputs: d_in[0] grid f32[384^3], d_in[1] survive int32[27],
//         d_in[2] birth int32[27], d_in[3] num_models (unused)
// Output: float32 [out_size]

#define DIM 384

__global__ __launch_bounds__(64, 1)
void ca_first_cells_kernel(const float* __restrict__ grid,
                           const int* __restrict__ survive_mask,
                           const int* __restrict__ birth_mask,
                           float* __restrict__ out) {
    const int i = threadIdx.x;            // cell index, 0..63
    const unsigned lane = (unsigned)i & 31u;

    // Rule-table loads first: independent, resolve inside the same memory
    // round trip as the grid loads.
    const unsigned mi = lane < 27u ? lane : 26u;
    const int sv = survive_mask[mi];
    const int bv = birth_mask[mi];

    // Cell (0, 0, z=i). Low-side wrap only at z=0; high side never wraps
    // (i <= 63 << DIM-1).
    const int z = i;
    const int zm1 = (z == 0) ? (DIM - 1) : (z - 1);
    const int zp1 = z + 1;

    // 9 (x,y)-row base offsets for x=0, y=0: compile-time constants.
    const int rowoff[9] = {
        (DIM - 1) * DIM * DIM + (DIM - 1) * DIM,
        (DIM - 1) * DIM * DIM,
        (DIM - 1) * DIM * DIM + DIM,
        (DIM - 1) * DIM,
        0,
        DIM,
        DIM * DIM + (DIM - 1) * DIM,
        DIM * DIM,
        DIM * DIM + DIM,
    };

    // 27 independent loads, front-batched for max MLP (one latency round).
    float v[27];
#pragma unroll
    for (int r = 0; r < 9; r++) {
        v[r * 3 + 0] = __ldg(&grid[rowoff[r] + zm1]);
        v[r * 3 + 1] = __ldg(&grid[rowoff[r] + z]);
        v[r * 3 + 2] = __ldg(&grid[rowoff[r] + zp1]);
    }

    // Pack rule tables into register bitmasks (per-warp ballots); overlaps
    // with the in-flight grid loads.
    const unsigned valid = (lane < 27u);
    const unsigned sbits = __ballot_sync(0xffffffffu, (sv != 0) & valid);
    const unsigned bbits = __ballot_sync(0xffffffffu, (bv != 0) & valid);

    float s = 0.0f;
#pragma unroll
    for (int t = 0; t < 27; t++) s += v[t];

    const float center = v[13];           // (x=0, y=0, z) tap
    // 0/1 grid -> sum is an exact small integer; ci in [0, 26].
    const int ci = (int)(s - center + 0.5f);

    const unsigned bits = (center > 0.5f) ? sbits : bbits;
    out[i] = (float)((bits >> ci) & 1u);
}

extern "C" void kernel_launch(void* const* d_in, const int* in_sizes, int n_in,
                              void* d_out, int out_size) {
    const float* grid = (const float*)d_in[0];
    const int* survive_mask = (const int*)d_in[1];
    const int* birth_mask = (const int*)d_in[2];
    float* out = (float*)d_out;

    // out_size = 64: one block, one thread per output cell.
    ca_first_cells_kernel<<<1, 64>>>(grid, survive_mask, birth_mask, out);
}